// round 10
// baseline (speedup 1.0000x reference)
#include <cuda_runtime.h>

// Wealth_21182778704643 — GB300 sm_103a, R10
// R9 = 83.07us, DRAM 86%. R10 hides the wave-start staging bubble: the first
// 4 sigma LDG.128 are issued BEFORE the action/mu staging stores and consumed
// after the barrier — their ~600cyc DRAM latency overlaps staging+__syncthreads
// instead of being exposed at each of the 7 wave starts.

#define B_DIM 64
#define T_DIM 512
#define N_DIM 64
#define M_DIM 64

#define TB 16                 // time steps per block (one warp each)
#define THREADS 512
#define CHUNKS (T_DIM / TB)   // 32 blocks per b
#define MU_PAD 17

__device__ float    g_partial[B_DIM * CHUNKS];  // overwritten every run
__device__ unsigned g_count[B_DIM];             // 0 at load; restored to 0 every run

__device__ __forceinline__ float k_dt()  { return 1.0f / 252.0f; }
__device__ __forceinline__ float k_pen() { return 0.5f * 0.1f * (1.0f / 252.0f); } // GAMMA/2*DT

__global__ __launch_bounds__(THREADS, 2)
void wealth_main_kernel(const float* __restrict__ action,
                        const float* __restrict__ mu,
                        const float* __restrict__ sigma,
                        const float* __restrict__ zeta,
                        const float* __restrict__ bt,
                        float* __restrict__ out)
{
    __shared__ float a_s[TB * N_DIM];        // action[b, t0:t0+TB, :]   4 KB
    __shared__ float mu_s[N_DIM * MU_PAD];   // mu[b, :, t0:t0+TB] padded
    __shared__ float red_s[TB];              // per-warp contributions
    __shared__ int   last_s;

    const int b   = blockIdx.y;
    const int t0  = blockIdx.x * TB;
    const int tid = threadIdx.x;

    const int w    = tid >> 5;     // warp id = local time step 0..15
    const int lane = tid & 31;
    const int q    = lane & 15;    // m float4 group 0..15
    const int h    = lane >> 4;    // n half
    const int t    = t0 + w;

    // --- sigma base (pure register math, no smem dependency) ---
    const float4* sig4 = (const float4*)(sigma + (((size_t)b * T_DIM + t) * N_DIM) * M_DIM)
                         + (size_t)h * 32 * (M_DIM / 4) + q;

    // --- PREFETCH: first 4 sigma rows; latency hidden under staging+barrier ---
    const float4 pre0 = sig4[0 * (M_DIM / 4)];
    const float4 pre1 = sig4[1 * (M_DIM / 4)];
    const float4 pre2 = sig4[2 * (M_DIM / 4)];
    const float4 pre3 = sig4[3 * (M_DIM / 4)];

    // --- Stage action tile (contiguous 4 KB, coalesced) ---
    const float* ap = action + ((size_t)b * T_DIM + t0) * N_DIM;
    #pragma unroll
    for (int i = tid; i < TB * N_DIM; i += THREADS) a_s[i] = ap[i];

    // --- Stage mu tile: mu[b, n, t0+tl] (16 consecutive t per n) ---
    const float* mp = mu + (size_t)b * N_DIM * T_DIM + t0;
    #pragma unroll
    for (int i = tid; i < N_DIM * TB; i += THREADS) {
        int n  = i >> 4;
        int tl = i & 15;
        mu_s[n * MU_PAD + tl] = mp[(size_t)n * T_DIM + tl];
    }
    __syncthreads();

    // --- hoisted independent loads: in flight during the whole sigma loop ---
    const float4 z   = ((const float4*)(zeta + ((size_t)b * T_DIM + t) * M_DIM))[q];
    const float  btv = __ldg(bt + t);

    const float4* ag4 = (const float4*)(a_s + w * N_DIM + h * 32);   // 128B-aligned

    float4 acc = make_float4(0.f, 0.f, 0.f, 0.f);

    // --- first 4 n's consume the prefetched values ---
    {
        const float4 av = ag4[0];
        acc.x = fmaf(av.x, pre0.x, acc.x); acc.y = fmaf(av.x, pre0.y, acc.y);
        acc.z = fmaf(av.x, pre0.z, acc.z); acc.w = fmaf(av.x, pre0.w, acc.w);
        acc.x = fmaf(av.y, pre1.x, acc.x); acc.y = fmaf(av.y, pre1.y, acc.y);
        acc.z = fmaf(av.y, pre1.z, acc.z); acc.w = fmaf(av.y, pre1.w, acc.w);
        acc.x = fmaf(av.z, pre2.x, acc.x); acc.y = fmaf(av.z, pre2.y, acc.y);
        acc.z = fmaf(av.z, pre2.z, acc.z); acc.w = fmaf(av.z, pre2.w, acc.w);
        acc.x = fmaf(av.w, pre3.x, acc.x); acc.y = fmaf(av.w, pre3.y, acc.y);
        acc.z = fmaf(av.w, pre3.z, acc.z); acc.w = fmaf(av.w, pre3.w, acc.w);
    }

    // --- remaining 28 n's stream normally ---
    #pragma unroll
    for (int n4 = 1; n4 < 8; ++n4) {
        const float4 av = ag4[n4];   // one LDS.128 covers 4 n's
        #pragma unroll
        for (int j = 0; j < 4; ++j) {
            const float  an = (j == 0) ? av.x : (j == 1) ? av.y : (j == 2) ? av.z : av.w;
            const float4 s  = sig4[(n4 * 4 + j) * (M_DIM / 4)];
            acc.x = fmaf(an, s.x, acc.x);
            acc.y = fmaf(an, s.y, acc.y);
            acc.z = fmaf(an, s.z, acc.z);
            acc.w = fmaf(an, s.w, acc.w);
        }
    }

    // --- combine the two n-halves (acc complete over n before squaring) ---
    acc.x += __shfl_xor_sync(0xffffffffu, acc.x, 16);
    acc.y += __shfl_xor_sync(0xffffffffu, acc.y, 16);
    acc.z += __shfl_xor_sync(0xffffffffu, acc.z, 16);
    acc.w += __shfl_xor_sync(0xffffffffu, acc.w, 16);

    // --- (risk + zeta)^2 partial for this m-quad ---
    const float vx = acc.x + z.x;
    const float vy = acc.y + z.y;
    const float vz = acc.z + z.z;
    const float vw = acc.w + z.w;
    float sq = vx * vx + vy * vy + vz * vz + vw * vw;

    #pragma unroll
    for (int off = 8; off; off >>= 1)
        sq += __shfl_xor_sync(0xffffffffu, sq, off, 16);

    // --- wealth dot partial: each lane covers n = h*32 + 2q, 2q+1 ---
    const int n0 = h * 32 + q * 2;
    float wp = fmaf(a_s[w * N_DIM + n0],      mu_s[n0 * MU_PAD + w],
                    a_s[w * N_DIM + n0 + 1] * mu_s[(n0 + 1) * MU_PAD + w]);
    #pragma unroll
    for (int off = 16; off; off >>= 1)
        wp += __shfl_xor_sync(0xffffffffu, wp, off);

    if (lane == 0) {
        const float rw = wp + btv;
        red_s[w] = k_dt() * rw - k_pen() * sq;
    }
    __syncthreads();

    // --- block partial: warp 0 reduces 16 warp contributions ---
    if (w == 0) {
        float v = (lane < TB) ? red_s[lane] : 0.0f;
        #pragma unroll
        for (int off = 8; off; off >>= 1)
            v += __shfl_xor_sync(0xffffffffu, v, off, 16);
        if (lane == 0) {
            g_partial[b * CHUNKS + blockIdx.x] = v;
            __threadfence();                       // release partial before count
            unsigned old = atomicAdd(&g_count[b], 1u);
            last_s = (old == CHUNKS - 1);
        }
    }
    __syncthreads();

    // --- last block for this b: sum the 32 partials, write out, reset counter ---
    if (last_s && w == 0) {
        float v = __ldcg(&g_partial[b * CHUNKS + lane]);
        #pragma unroll
        for (int off = 16; off; off >>= 1)
            v += __shfl_xor_sync(0xffffffffu, v, off);
        if (lane == 0) {
            out[b] = v;
            atomicExch(&g_count[b], 0u);   // restore invariant for next replay
        }
    }
}

extern "C" void kernel_launch(void* const* d_in, const int* in_sizes, int n_in,
                              void* d_out, int out_size)
{
    const float* action = (const float*)d_in[0];  // (B, T, N)
    const float* mu     = (const float*)d_in[1];  // (B, N, T)
    const float* sigma  = (const float*)d_in[2];  // (B, T, N, M)
    const float* zeta   = (const float*)d_in[3];  // (B, T, M)
    const float* bt     = (const float*)d_in[4];  // (T, 1)
    float* out          = (float*)d_out;          // (B,)

    (void)in_sizes; (void)n_in; (void)out_size;

    dim3 grid(CHUNKS, B_DIM);
    wealth_main_kernel<<<grid, THREADS>>>(action, mu, sigma, zeta, bt, out);
}

// round 11
// speedup vs baseline: 1.0202x; 1.0202x over previous
#include <cuda_runtime.h>

// Wealth_21182778704643 — GB300 sm_103a, R11
// R9 = 83.07us (DRAM 86.0%) is the proven skeleton. R10's 4-row prefetch
// regressed (register pressure at the 64-reg cap). R11 = R9 hot loop verbatim
// + slimmer epilogue: second __syncthreads and last_s smem flag removed
// (warp0 keeps the last-block flag in a register), and __threadfence+atomicAdd
// fused into a single atom.acq_rel.gpu.add.

#define B_DIM 64
#define T_DIM 512
#define N_DIM 64
#define M_DIM 64

#define TB 16                 // time steps per block (one warp each)
#define THREADS 512
#define CHUNKS (T_DIM / TB)   // 32 blocks per b
#define MU_PAD 17

__device__ float    g_partial[B_DIM * CHUNKS];  // overwritten every run
__device__ unsigned g_count[B_DIM];             // 0 at load; restored to 0 every run

__device__ __forceinline__ float k_dt()  { return 1.0f / 252.0f; }
__device__ __forceinline__ float k_pen() { return 0.5f * 0.1f * (1.0f / 252.0f); } // GAMMA/2*DT

__global__ __launch_bounds__(THREADS, 2)
void wealth_main_kernel(const float* __restrict__ action,
                        const float* __restrict__ mu,
                        const float* __restrict__ sigma,
                        const float* __restrict__ zeta,
                        const float* __restrict__ bt,
                        float* __restrict__ out)
{
    __shared__ float a_s[TB * N_DIM];        // action[b, t0:t0+TB, :]   4 KB
    __shared__ float mu_s[N_DIM * MU_PAD];   // mu[b, :, t0:t0+TB] padded
    __shared__ float red_s[TB];              // per-warp contributions

    const int b   = blockIdx.y;
    const int t0  = blockIdx.x * TB;
    const int tid = threadIdx.x;

    // --- Stage action tile (contiguous 4 KB, coalesced) ---
    const float* ap = action + ((size_t)b * T_DIM + t0) * N_DIM;
    #pragma unroll
    for (int i = tid; i < TB * N_DIM; i += THREADS) a_s[i] = ap[i];

    // --- Stage mu tile: mu[b, n, t0+tl] (16 consecutive t per n) ---
    const float* mp = mu + (size_t)b * N_DIM * T_DIM + t0;
    #pragma unroll
    for (int i = tid; i < N_DIM * TB; i += THREADS) {
        int n  = i >> 4;
        int tl = i & 15;
        mu_s[n * MU_PAD + tl] = mp[(size_t)n * T_DIM + tl];
    }
    __syncthreads();

    const int w    = tid >> 5;     // warp id = local time step 0..15
    const int lane = tid & 31;
    const int q    = lane & 15;    // m float4 group 0..15
    const int h    = lane >> 4;    // n half
    const int t    = t0 + w;

    // --- hoisted independent loads: in flight during the whole sigma loop ---
    const float4 z   = ((const float4*)(zeta + ((size_t)b * T_DIM + t) * M_DIM))[q];
    const float  btv = __ldg(bt + t);

    // --- Stream sigma[b, t, h*32 + n', 4q..4q+3], n' = 0..31 ---
    const float4* sig4 = (const float4*)(sigma + (((size_t)b * T_DIM + t) * N_DIM) * M_DIM)
                         + (size_t)h * 32 * (M_DIM / 4) + q;
    const float4* ag4  = (const float4*)(a_s + w * N_DIM + h * 32);   // 128B-aligned

    float4 acc = make_float4(0.f, 0.f, 0.f, 0.f);
    #pragma unroll
    for (int n4 = 0; n4 < 8; ++n4) {
        const float4 av = ag4[n4];   // one LDS.128 covers 4 n's
        #pragma unroll
        for (int j = 0; j < 4; ++j) {
            const float  an = (j == 0) ? av.x : (j == 1) ? av.y : (j == 2) ? av.z : av.w;
            const float4 s  = sig4[(n4 * 4 + j) * (M_DIM / 4)];
            acc.x = fmaf(an, s.x, acc.x);
            acc.y = fmaf(an, s.y, acc.y);
            acc.z = fmaf(an, s.z, acc.z);
            acc.w = fmaf(an, s.w, acc.w);
        }
    }

    // --- combine the two n-halves (acc complete over n before squaring) ---
    acc.x += __shfl_xor_sync(0xffffffffu, acc.x, 16);
    acc.y += __shfl_xor_sync(0xffffffffu, acc.y, 16);
    acc.z += __shfl_xor_sync(0xffffffffu, acc.z, 16);
    acc.w += __shfl_xor_sync(0xffffffffu, acc.w, 16);

    // --- (risk + zeta)^2 partial for this m-quad ---
    const float vx = acc.x + z.x;
    const float vy = acc.y + z.y;
    const float vz = acc.z + z.z;
    const float vw = acc.w + z.w;
    float sq = vx * vx + vy * vy + vz * vz + vw * vw;

    #pragma unroll
    for (int off = 8; off; off >>= 1)
        sq += __shfl_xor_sync(0xffffffffu, sq, off, 16);

    // --- wealth dot partial: each lane covers n = h*32 + 2q, 2q+1 ---
    const int n0 = h * 32 + q * 2;
    float wp = fmaf(a_s[w * N_DIM + n0],      mu_s[n0 * MU_PAD + w],
                    a_s[w * N_DIM + n0 + 1] * mu_s[(n0 + 1) * MU_PAD + w]);
    #pragma unroll
    for (int off = 16; off; off >>= 1)
        wp += __shfl_xor_sync(0xffffffffu, wp, off);

    if (lane == 0) {
        const float rw = wp + btv;
        red_s[w] = k_dt() * rw - k_pen() * sq;
    }
    __syncthreads();   // red_s visible to warp 0; warps 1..15 are done after this

    if (w == 0) {
        // block partial: warp 0 reduces the 16 warp contributions
        float v = (lane < TB) ? red_s[lane] : 0.0f;
        #pragma unroll
        for (int off = 8; off; off >>= 1)
            v += __shfl_xor_sync(0xffffffffu, v, off, 16);

        unsigned old = 0;
        if (lane == 0) {
            g_partial[b * CHUNKS + blockIdx.x] = v;
            // fused release (orders the partial store) + acquire (pairs with
            // the other 31 blocks' releases for the winner's reads below)
            asm volatile("atom.acq_rel.gpu.add.u32 %0, [%1], %2;"
                         : "=r"(old)
                         : "l"(&g_count[b]), "r"(1u)
                         : "memory");
        }
        const unsigned last = __shfl_sync(0xffffffffu, (old == CHUNKS - 1) ? 1u : 0u, 0);

        if (last) {
            float p = __ldcg(&g_partial[b * CHUNKS + lane]);   // 32 partials
            #pragma unroll
            for (int off = 16; off; off >>= 1)
                p += __shfl_xor_sync(0xffffffffu, p, off);
            if (lane == 0) {
                out[b] = p;
                atomicExch(&g_count[b], 0u);   // restore invariant for next replay
            }
        }
    }
}

extern "C" void kernel_launch(void* const* d_in, const int* in_sizes, int n_in,
                              void* d_out, int out_size)
{
    const float* action = (const float*)d_in[0];  // (B, T, N)
    const float* mu     = (const float*)d_in[1];  // (B, N, T)
    const float* sigma  = (const float*)d_in[2];  // (B, T, N, M)
    const float* zeta   = (const float*)d_in[3];  // (B, T, M)
    const float* bt     = (const float*)d_in[4];  // (T, 1)
    float* out          = (float*)d_out;          // (B,)

    (void)in_sizes; (void)n_in; (void)out_size;

    dim3 grid(CHUNKS, B_DIM);
    wealth_main_kernel<<<grid, THREADS>>>(action, mu, sigma, zeta, bt, out);
}